// round 3
// baseline (speedup 1.0000x reference)
#include <cuda_runtime.h>

// Problem shape (fixed by reference): image [8,512,512,32] f32, slic [8,512,512,1] i32 in [1,256]
// out [8,256,32] f32 = segment_sum(image) / segment_count_nonzero(image) per channel.

#define BATCH 8
#define HW    (512*512)          // pixels per image
#define C     32                 // channels
#define S     256                // segments
#define BLOCKS_PER_IMG 111       // 111*8 = 888 blocks = 6 per SM (148 SMs)
#define THREADS 256

// Scratch: __device__ globals (no allocation allowed anywhere).
__device__ float g_sums[BATCH * S * C];   // 256 KB
__device__ float g_zero[BATCH * S * C];   // zero-value corrections (rarely touched)
__device__ float g_pix [BATCH * S];       // pixel count per (image, segment)

// ---------------------------------------------------------------------------
// Kernel 1: zero the scratch (must run every graph replay).
// ---------------------------------------------------------------------------
__global__ void zero_scratch() {
    int i = blockIdx.x * blockDim.x + threadIdx.x;
    if (i < BATCH * S * C) {
        g_sums[i] = 0.0f;
        g_zero[i] = 0.0f;
    }
    if (i < BATCH * S) g_pix[i] = 0.0f;
}

// ---------------------------------------------------------------------------
// Kernel 2: privatized scatter-reduce.
//   grid = (BLOCKS_PER_IMG, BATCH), block = 256 threads.
//   Thread layout: 8 threads per pixel, each owns a float4 channel-quad.
//   => warp = 4 consecutive pixels, LDG.128 fully coalesced (512B/warp),
//      shared atomics land on 32 distinct consecutive banks (conflict-free).
//   Counts: 1 pixel-count atomic per pixel + per-channel zero correction
//   (exact count_nonzero semantics; zero branch essentially never taken).
// ---------------------------------------------------------------------------
__global__ void __launch_bounds__(THREADS)
seg_accum(const float* __restrict__ img, const int* __restrict__ slic) {
    __shared__ float s_sum[S * C];   // 32 KB
    __shared__ float s_pix[S];       // 1 KB

    const int b = blockIdx.y;

    for (int i = threadIdx.x; i < S * C; i += THREADS) s_sum[i] = 0.0f;
    if (threadIdx.x < S) s_pix[threadIdx.x] = 0.0f;
    __syncthreads();

    const int sub  = threadIdx.x & 7;    // which float4 of the 32 channels
    const int prow = threadIdx.x >> 3;   // pixel within the block's stripe

    const float4* __restrict__ imgb  = (const float4*)(img + (size_t)b * HW * C);
    const int*    __restrict__ slicb = slic + (size_t)b * HW;
    float* __restrict__ gz = g_zero + (size_t)b * S * C;

    const int stride = BLOCKS_PER_IMG * (THREADS / 8);

    #pragma unroll 4
    for (int p = blockIdx.x * (THREADS / 8) + prow; p < HW; p += stride) {
        const int    s = slicb[p] - 1;                 // 0-indexed segment
        const float4 v = imgb[(size_t)p * 8 + sub];    // 16B of this pixel's row
        const int base = s * C + sub * 4;

        atomicAdd(&s_sum[base + 0], v.x);
        atomicAdd(&s_sum[base + 1], v.y);
        atomicAdd(&s_sum[base + 2], v.z);
        atomicAdd(&s_sum[base + 3], v.w);

        if (sub == 0) atomicAdd(&s_pix[s], 1.0f);

        // Exact count_nonzero: correct for values that are exactly zero.
        if (v.x == 0.0f) atomicAdd(&gz[base + 0], 1.0f);
        if (v.y == 0.0f) atomicAdd(&gz[base + 1], 1.0f);
        if (v.z == 0.0f) atomicAdd(&gz[base + 2], 1.0f);
        if (v.w == 0.0f) atomicAdd(&gz[base + 3], 1.0f);
    }
    __syncthreads();

    // Flush block-private accumulators to global (spread REDG, cheap).
    float* __restrict__ gs = g_sums + (size_t)b * S * C;
    for (int i = threadIdx.x; i < S * C; i += THREADS)
        atomicAdd(&gs[i], s_sum[i]);
    if (threadIdx.x < S)
        atomicAdd(&g_pix[b * S + threadIdx.x], s_pix[threadIdx.x]);
}

// ---------------------------------------------------------------------------
// Kernel 3: out = sum / (pixel_count - zero_count)   [65536 elements]
// ---------------------------------------------------------------------------
__global__ void finalize(float* __restrict__ out) {
    int i = blockIdx.x * blockDim.x + threadIdx.x;
    if (i < BATCH * S * C) {
        float cnt = g_pix[i >> 5] - g_zero[i];
        out[i] = g_sums[i] / cnt;
    }
}

// ---------------------------------------------------------------------------
// Entry point (graph-capturable: kernel launches only, no sync, no alloc).
// ---------------------------------------------------------------------------
extern "C" void kernel_launch(void* const* d_in, const int* in_sizes, int n_in,
                              void* d_out, int out_size) {
    const float* img  = (const float*)d_in[0];   // image, 67108864 f32
    const int*   slic = (const int*)  d_in[1];   // slic,   2097152 i32
    float*       out  = (float*)d_out;           // 65536 f32

    (void)in_sizes; (void)n_in; (void)out_size; (void)out;

    zero_scratch<<<(BATCH * S * C + 255) / 256, 256>>>();

    dim3 grid(BLOCKS_PER_IMG, BATCH);
    seg_accum<<<grid, THREADS>>>(img, slic);

    finalize<<<(BATCH * S * C + 255) / 256, 256>>>(out);
}

// round 4
// speedup vs baseline: 1.5369x; 1.5369x over previous
#include <cuda_runtime.h>

// image [8,512,512,32] f32, slic [8,512,512,1] i32 in [1,256]
// out [8,256,32] f32 = segment_sum(image) / segment_count_nonzero(image) per channel.

#define BATCH 8
#define HW    (512*512)
#define C     32
#define S     256
#define CS    33                 // skewed stride: bank = (s + c) mod 32 -> conflict-free atomics
#define BLOCKS_PER_IMG 37        // 37*8 = 296 blocks = 2 per SM (148 SMs), 64 warps/SM
#define THREADS 1024

__device__ float g_sums[BATCH * S * C];   // 256 KB
__device__ float g_zero[BATCH * S * C];   // zero-value corrections (rarely touched)
__device__ float g_pix [BATCH * S];       // pixel count per (image, segment)

// ---------------------------------------------------------------------------
// Kernel 1: zero the scratch (must run every graph replay).
// ---------------------------------------------------------------------------
__global__ void zero_scratch() {
    int i = blockIdx.x * blockDim.x + threadIdx.x;
    if (i < BATCH * S * C) {
        g_sums[i] = 0.0f;
        g_zero[i] = 0.0f;
    }
    if (i < BATCH * S) g_pix[i] = 0.0f;
}

// ---------------------------------------------------------------------------
// Kernel 2: privatized scatter-reduce with skewed shared accumulator.
//   grid = (37, 8), block = 1024 threads. 8 threads per pixel, each owns a
//   float4 channel-quad (LDG.128, 512B/warp coalesced).
//   Shared layout s*33 + c makes the bank depend on the segment id, so the
//   4 pixels per warp (random segments) hit distinct banks -> ~conflict-free
//   shared atomics, vs guaranteed 4-way conflicts with stride 32.
//   Counts: 1 pixel-count atomic per pixel + per-channel zero correction
//   (exact count_nonzero semantics; zero branch essentially never fires for
//   gaussian data but keeps bit-exact semantics).
// ---------------------------------------------------------------------------
__global__ void __launch_bounds__(THREADS, 2)
seg_accum(const float* __restrict__ img, const int* __restrict__ slic) {
    __shared__ float s_sum[S * CS];  // 33 KB, skewed
    __shared__ float s_pix[S];       // 1 KB

    const int b = blockIdx.y;

    for (int i = threadIdx.x; i < S * CS; i += THREADS) s_sum[i] = 0.0f;
    if (threadIdx.x < S) s_pix[threadIdx.x] = 0.0f;
    __syncthreads();

    const int sub  = threadIdx.x & 7;    // which float4 of the 32 channels
    const int prow = threadIdx.x >> 3;   // pixel within the block's stripe

    const float4* __restrict__ imgb  = (const float4*)(img + (size_t)b * HW * C);
    const int*    __restrict__ slicb = slic + (size_t)b * HW;
    float* __restrict__ gz = g_zero + (size_t)b * S * C;

    const int stride = BLOCKS_PER_IMG * (THREADS / 8);

    #pragma unroll 4
    for (int p = blockIdx.x * (THREADS / 8) + prow; p < HW; p += stride) {
        const int    s = slicb[p] - 1;                 // 0-indexed segment
        const float4 v = imgb[(size_t)p * 8 + sub];    // 16B of this pixel's row
        const int sbase = s * CS + sub * 4;            // skewed shared index

        atomicAdd(&s_sum[sbase + 0], v.x);
        atomicAdd(&s_sum[sbase + 1], v.y);
        atomicAdd(&s_sum[sbase + 2], v.z);
        atomicAdd(&s_sum[sbase + 3], v.w);

        if (sub == 0) atomicAdd(&s_pix[s], 1.0f);

        // Exact count_nonzero: correct for values that are exactly zero.
        const int gbase = s * C + sub * 4;
        if (v.x == 0.0f) atomicAdd(&gz[gbase + 0], 1.0f);
        if (v.y == 0.0f) atomicAdd(&gz[gbase + 1], 1.0f);
        if (v.z == 0.0f) atomicAdd(&gz[gbase + 2], 1.0f);
        if (v.w == 0.0f) atomicAdd(&gz[gbase + 3], 1.0f);
    }
    __syncthreads();

    // Flush block-private accumulators to global (de-skew on the way out).
    // 296 blocks x 8448 lanes: ~2.5M REDG lanes total (~3x less than before).
    float* __restrict__ gs = g_sums + (size_t)b * S * C;
    for (int i = threadIdx.x; i < S * C; i += THREADS) {
        const int s = i >> 5, c = i & 31;
        atomicAdd(&gs[i], s_sum[s * CS + c]);
    }
    if (threadIdx.x < S)
        atomicAdd(&g_pix[b * S + threadIdx.x], s_pix[threadIdx.x]);
}

// ---------------------------------------------------------------------------
// Kernel 3: out = sum / (pixel_count - zero_count)   [65536 elements]
// ---------------------------------------------------------------------------
__global__ void finalize(float* __restrict__ out) {
    int i = blockIdx.x * blockDim.x + threadIdx.x;
    if (i < BATCH * S * C) {
        float cnt = g_pix[i >> 5] - g_zero[i];
        out[i] = g_sums[i] / cnt;
    }
}

// ---------------------------------------------------------------------------
// Entry point (graph-capturable: kernel launches only, no sync, no alloc).
// ---------------------------------------------------------------------------
extern "C" void kernel_launch(void* const* d_in, const int* in_sizes, int n_in,
                              void* d_out, int out_size) {
    const float* img  = (const float*)d_in[0];   // image, 67108864 f32
    const int*   slic = (const int*)  d_in[1];   // slic,   2097152 i32
    float*       out  = (float*)d_out;           // 65536 f32

    (void)in_sizes; (void)n_in; (void)out_size;

    zero_scratch<<<(BATCH * S * C + 255) / 256, 256>>>();

    dim3 grid(BLOCKS_PER_IMG, BATCH);
    seg_accum<<<grid, THREADS>>>(img, slic);

    finalize<<<(BATCH * S * C + 255) / 256, 256>>>(out);
}